// round 2
// baseline (speedup 1.0000x reference)
#include <cuda_runtime.h>
#include <cuda_bf16.h>
#include <cstdint>

// ---------------------------------------------------------------------------
// GQA: B=2, T=2048, C=1024, H=16 q-heads, KVH=4 kv-heads, D=64, causal, RoPE
// ---------------------------------------------------------------------------

__device__ __align__(16) float g_q[4194304];
__device__ __align__(16) float g_k[1048576];
__device__ __align__(16) float g_v[1048576];
__device__ __align__(16) float g_y[4194304];

// ---------------------------------------------------------------------------
// mma / ldmatrix helpers
// ---------------------------------------------------------------------------
__device__ __forceinline__ uint32_t smem_u32(const void* p) {
    return (uint32_t)__cvta_generic_to_shared(p);
}
__device__ __forceinline__ void ldmx4(uint32_t* r, uint32_t addr) {
    asm volatile("ldmatrix.sync.aligned.m8n8.x4.shared.b16 {%0,%1,%2,%3}, [%4];"
        : "=r"(r[0]), "=r"(r[1]), "=r"(r[2]), "=r"(r[3]) : "r"(addr));
}
__device__ __forceinline__ void ldmx4t(uint32_t* r, uint32_t addr) {
    asm volatile("ldmatrix.sync.aligned.m8n8.x4.trans.shared.b16 {%0,%1,%2,%3}, [%4];"
        : "=r"(r[0]), "=r"(r[1]), "=r"(r[2]), "=r"(r[3]) : "r"(addr));
}
__device__ __forceinline__ void mma_bf16(float* c, const uint32_t* a, const uint32_t* b) {
    asm volatile(
        "mma.sync.aligned.m16n8k16.row.col.f32.bf16.bf16.f32 "
        "{%0,%1,%2,%3}, {%4,%5,%6,%7}, {%8,%9}, {%0,%1,%2,%3};\n"
        : "+f"(c[0]), "+f"(c[1]), "+f"(c[2]), "+f"(c[3])
        : "r"(a[0]), "r"(a[1]), "r"(a[2]), "r"(a[3]), "r"(b[0]), "r"(b[1]));
}

// split a float4 into hi/lo bf16 pairs and store to two smem arrays
__device__ __forceinline__ void split_store(__nv_bfloat16* sh, __nv_bfloat16* sl,
                                            int off, float4 v) {
    __nv_bfloat162 h2, l2;
    __nv_bfloat16 h;
    h = __float2bfloat16(v.x); h2.x = h; l2.x = __float2bfloat16(v.x - __bfloat162float(h));
    h = __float2bfloat16(v.y); h2.y = h; l2.y = __float2bfloat16(v.y - __bfloat162float(h));
    *(__nv_bfloat162*)(sh + off)     = h2;
    *(__nv_bfloat162*)(sl + off)     = l2;
    h = __float2bfloat16(v.z); h2.x = h; l2.x = __float2bfloat16(v.z - __bfloat162float(h));
    h = __float2bfloat16(v.w); h2.y = h; l2.y = __float2bfloat16(v.w - __bfloat162float(h));
    *(__nv_bfloat162*)(sh + off + 2) = h2;
    *(__nv_bfloat162*)(sl + off + 2) = l2;
}

__device__ __forceinline__ void qkv_scatter(int r, int c, float v0, float v1) {
    int b = r >> 11, t = r & 2047;
    float2 v; v.x = v0; v.y = v1;
    if (c < 1024) {
        int h = c >> 6, d = c & 63;
        *(float2*)&g_q[(((b * 16 + h) * 2048 + t) << 6) + d] = v;
    } else if (c < 1280) {
        int c2 = c - 1024; int h = c2 >> 6, d = c2 & 63;
        *(float2*)&g_k[(((b * 4 + h) * 2048 + t) << 6) + d] = v;
    } else {
        int c2 = c - 1280; int h = c2 >> 6, d = c2 & 63;
        *(float2*)&g_v[(((b * 4 + h) * 2048 + t) << 6) + d] = v;
    }
}

// ---------------------------------------------------------------------------
// bf16x3 GEMM (fp32-accurate via hi/lo split, HMMA tensor path).
// CTA: 256 thr (8 warps, 4x2), tile 128x128, BK=32.
// MODE 0: A=x, B=[Wq|Wk|Wv] (N=1536), scatter epilogue into g_q/g_k/g_v.
// MODE 1: A=g_y, B=Wo (N=1024), plain epilogue into Cout.
// A smem rows padded to 80B (40 halves), B rows to 272B (136 halves):
// ldmatrix 8-row groups hit distinct 16B bank-groups.
// ---------------------------------------------------------------------------
template<int MODE>
__global__ void __launch_bounds__(256, 1) gemm_bf16x3(
    const float* __restrict__ A,
    const float* __restrict__ B0,
    const float* __restrict__ B1,
    const float* __restrict__ B2,
    float* __restrict__ Cout)
{
    __shared__ __align__(16) __nv_bfloat16 sAh[128 * 40];
    __shared__ __align__(16) __nv_bfloat16 sAl[128 * 40];
    __shared__ __align__(16) __nv_bfloat16 sBh[32 * 136];
    __shared__ __align__(16) __nv_bfloat16 sBl[32 * 136];

    int tid  = threadIdx.x;
    int lane = tid & 31;
    int warp = tid >> 5;
    int wm   = warp >> 1;      // 0..3
    int wn   = warp & 1;       // 0..1
    int brow = blockIdx.y * 128;
    int bcol = blockIdx.x * 128;

    const float* Bmat; int ldb, bc0;
    if (MODE == 1) { Bmat = B0; ldb = 1024; bc0 = bcol; }
    else {
        if (bcol < 1024)      { Bmat = B0; ldb = 1024; bc0 = bcol;        }
        else if (bcol < 1280) { Bmat = B1; ldb = 256;  bc0 = bcol - 1024; }
        else                  { Bmat = B2; ldb = 256;  bc0 = bcol - 1280; }
    }

    float c[2][8][4];
    #pragma unroll
    for (int mt = 0; mt < 2; mt++)
        #pragma unroll
        for (int nt = 0; nt < 8; nt++)
            #pragma unroll
            for (int i = 0; i < 4; i++) c[mt][nt][i] = 0.f;

    // prefetch first K-slab into registers
    float4 pa[4], pb[4];
    #pragma unroll
    for (int i = 0; i < 4; i++) {
        int f = tid + i * 256;
        pa[i] = *(const float4*)(A + (brow + (f >> 3)) * 1024 + ((f & 7) << 2));
        pb[i] = *(const float4*)(Bmat + (f >> 5) * ldb + bc0 + ((f & 31) << 2));
    }

    uint32_t aHb = smem_u32(sAh), aLb = smem_u32(sAl);
    uint32_t bHb = smem_u32(sBh), bLb = smem_u32(sBl);

    for (int kb = 0; kb < 1024; kb += 32) {
        __syncthreads();
        #pragma unroll
        for (int i = 0; i < 4; i++) {
            int f = tid + i * 256;
            split_store(sAh, sAl, (f >> 3) * 40 + ((f & 7) << 2), pa[i]);
            split_store(sBh, sBl, (f >> 5) * 136 + ((f & 31) << 2), pb[i]);
        }
        __syncthreads();

        if (kb + 32 < 1024) {
            #pragma unroll
            for (int i = 0; i < 4; i++) {
                int f = tid + i * 256;
                pa[i] = *(const float4*)(A + (brow + (f >> 3)) * 1024 + kb + 32 + ((f & 7) << 2));
                pb[i] = *(const float4*)(Bmat + (kb + 32 + (f >> 5)) * ldb + bc0 + ((f & 31) << 2));
            }
        }

        #pragma unroll
        for (int ks = 0; ks < 2; ks++) {
            uint32_t aH[2][4], aL[2][4], bH[4][4], bL[4][4];
            #pragma unroll
            for (int mt = 0; mt < 2; mt++) {
                uint32_t off = 2u * ((uint32_t)(wm * 32 + mt * 16 + (lane & 15)) * 40
                                     + ks * 16 + ((lane >> 4) << 3));
                ldmx4(aH[mt], aHb + off);
                ldmx4(aL[mt], aLb + off);
            }
            #pragma unroll
            for (int np = 0; np < 4; np++) {
                uint32_t off = 2u * ((uint32_t)(ks * 16 + (lane & 15)) * 136
                                     + wn * 64 + np * 16 + ((lane >> 4) << 3));
                ldmx4t(bH[np], bHb + off);
                ldmx4t(bL[np], bLb + off);
            }
            #pragma unroll
            for (int mt = 0; mt < 2; mt++)
                #pragma unroll
                for (int nt = 0; nt < 8; nt++) {
                    const uint32_t* bh = &bH[nt >> 1][(nt & 1) * 2];
                    const uint32_t* bl = &bL[nt >> 1][(nt & 1) * 2];
                    mma_bf16(c[mt][nt], aH[mt], bh);   // hi*hi
                    mma_bf16(c[mt][nt], aH[mt], bl);   // hi*lo
                    mma_bf16(c[mt][nt], aL[mt], bh);   // lo*hi
                }
        }
    }

    // epilogue
    #pragma unroll
    for (int mt = 0; mt < 2; mt++) {
        int r0 = brow + wm * 32 + mt * 16 + (lane >> 2);
        #pragma unroll
        for (int nt = 0; nt < 8; nt++) {
            int cc = bcol + wn * 64 + nt * 8 + ((lane & 3) << 1);
            if (MODE == 1) {
                float2 v0; v0.x = c[mt][nt][0]; v0.y = c[mt][nt][1];
                float2 v1; v1.x = c[mt][nt][2]; v1.y = c[mt][nt][3];
                *(float2*)(Cout + r0 * 1024 + cc)       = v0;
                *(float2*)(Cout + (r0 + 8) * 1024 + cc) = v1;
            } else {
                qkv_scatter(r0,     cc, c[mt][nt][0], c[mt][nt][1]);
                qkv_scatter(r0 + 8, cc, c[mt][nt][2], c[mt][nt][3]);
            }
        }
    }
}

// ---------------------------------------------------------------------------
// In-place RoPE on g_q (which=0) or g_k (which=1).
// ---------------------------------------------------------------------------
__global__ void rope_kernel(const float* __restrict__ cosb,
                            const float* __restrict__ sinb,
                            int n, int which)
{
    int i = blockIdx.x * blockDim.x + threadIdx.x;
    if (i >= n) return;
    float* buf = which ? g_k : g_q;
    int d  = i & 31;
    int t  = (i >> 5) & 2047;
    int bh = i >> 16;
    float* base = buf + ((bh * 2048 + t) << 6);
    float c = cosb[t * 32 + d];
    float s = sinb[t * 32 + d];
    float x1 = base[d], x2 = base[d + 32];
    base[d]      = x1 * c - x2 * s;
    base[d + 32] = x2 * c + x1 * s;
}

// ---------------------------------------------------------------------------
// Causal flash attention, fp32, split-D:
// 256 threads, 128 q rows per CTA, 2 threads per row (each owns 32 of 64 dims).
// Full score recovered via shfl.xor(1). K/V tiles of 64 rows in smem.
// grid = (T/128, B*H), block = 256.
// ---------------------------------------------------------------------------
__global__ void __launch_bounds__(256) attn_kernel()
{
    __shared__ __align__(16) float ks[64 * 64];
    __shared__ __align__(16) float vs[64 * 64];

    int tid  = threadIdx.x;
    int bh   = blockIdx.y;          // 0..31
    int b    = bh >> 4, hh = bh & 15;
    int kh   = hh >> 2;
    int half = tid & 1;
    int rloc = tid >> 1;            // 0..127
    int tq   = blockIdx.x * 128 + rloc;
    int warp = tid >> 5;

    // q half-row, scale 1/8 folded in
    float qr[32];
    const float4* qrow = (const float4*)(g_q + ((bh * 2048 + tq) << 6) + half * 32);
    #pragma unroll
    for (int i = 0; i < 8; i++) {
        float4 t4 = qrow[i];
        qr[i*4+0] = t4.x * 0.125f; qr[i*4+1] = t4.y * 0.125f;
        qr[i*4+2] = t4.z * 0.125f; qr[i*4+3] = t4.w * 0.125f;
    }
    float o[32];
    #pragma unroll
    for (int i = 0; i < 32; i++) o[i] = 0.f;
    float m = -1e30f, l = 0.f;

    const float* kbase = g_k + (((b * 4 + kh) * 2048) << 6);
    const float* vbase = g_v + (((b * 4 + kh) * 2048) << 6);

    // highest q row handled by this warp (warp-uniform loop bound)
    int tq_hi = blockIdx.x * 128 + warp * 16 + 15;

    int ntiles = blockIdx.x * 2 + 2;
    for (int kt = 0; kt < ntiles; kt++) {
        __syncthreads();
        const float4* ksrc = (const float4*)(kbase + kt * 4096);
        const float4* vsrc = (const float4*)(vbase + kt * 4096);
        #pragma unroll
        for (int i = 0; i < 4; i++) {
            int f = tid + i * 256;              // 0..1023 float4s
            ((float4*)ks)[f] = ksrc[f];
            ((float4*)vs)[f] = vsrc[f];
        }
        __syncthreads();

        int base = kt * 64;
        int jw = tq_hi - base + 1; if (jw > 64) jw = 64;   // warp-uniform
        int jm = tq - base + 1;    if (jm > 64) jm = 64;   // per-row causal bound

        for (int j = 0; j < jw; j++) {
            const float4* krow = (const float4*)(ks + j * 64 + half * 32);
            float s0 = 0.f, s1 = 0.f, s2 = 0.f, s3 = 0.f;
            #pragma unroll
            for (int d4 = 0; d4 < 8; d4++) {
                float4 k4 = krow[d4];
                s0 += qr[d4*4+0] * k4.x;
                s1 += qr[d4*4+1] * k4.y;
                s2 += qr[d4*4+2] * k4.z;
                s3 += qr[d4*4+3] * k4.w;
            }
            float sp = (s0 + s1) + (s2 + s3);
            float s  = sp + __shfl_xor_sync(0xffffffffu, sp, 1);
            if (j < jm) {
                const float4* vrow = (const float4*)(vs + j * 64 + half * 32);
                if (s <= m) {
                    float p = __expf(s - m);
                    l += p;
                    #pragma unroll
                    for (int d4 = 0; d4 < 8; d4++) {
                        float4 v4 = vrow[d4];
                        o[d4*4+0] += p * v4.x; o[d4*4+1] += p * v4.y;
                        o[d4*4+2] += p * v4.z; o[d4*4+3] += p * v4.w;
                    }
                } else {
                    float corr = __expf(m - s);
                    m = s;
                    l = l * corr + 1.f;
                    #pragma unroll
                    for (int d4 = 0; d4 < 8; d4++) {
                        float4 v4 = vrow[d4];
                        o[d4*4+0] = o[d4*4+0] * corr + v4.x;
                        o[d4*4+1] = o[d4*4+1] * corr + v4.y;
                        o[d4*4+2] = o[d4*4+2] * corr + v4.z;
                        o[d4*4+3] = o[d4*4+3] * corr + v4.w;
                    }
                }
            }
        }
    }

    float inv = 1.f / l;
    float4* yrow = (float4*)(g_y + (b * 2048 + tq) * 1024 + hh * 64 + half * 32);
    #pragma unroll
    for (int i = 0; i < 8; i++) {
        float4 t4;
        t4.x = o[i*4+0] * inv; t4.y = o[i*4+1] * inv;
        t4.z = o[i*4+2] * inv; t4.w = o[i*4+3] * inv;
        yrow[i] = t4;
    }
}

// ---------------------------------------------------------------------------
// Launch: x, cos, sin, Wq, Wk, Wv, Wo. out = f32 [B,T,C].
// ---------------------------------------------------------------------------
extern "C" void kernel_launch(void* const* d_in, const int* in_sizes, int n_in,
                              void* d_out, int out_size)
{
    const float* x    = (const float*)d_in[0];
    const float* cosb = (const float*)d_in[1];
    const float* sinb = (const float*)d_in[2];
    const float* Wq   = (const float*)d_in[3];
    const float* Wk   = (const float*)d_in[4];
    const float* Wv   = (const float*)d_in[5];
    const float* Wo   = (const float*)d_in[6];
    float* out = (float*)d_out;

    float* gy_dev = nullptr;
    cudaGetSymbolAddress((void**)&gy_dev, g_y);

    // 1. fused QKV projection (bf16x3 tensor cores)
    gemm_bf16x3<0><<<dim3(12, 32), 256>>>(x, Wq, Wk, Wv, nullptr);

    // 2/3. RoPE
    rope_kernel<<<8192, 256>>>(cosb, sinb, 2097152, 0);
    rope_kernel<<<2048, 256>>>(cosb, sinb, 524288, 1);

    // 4. causal attention (fp32, split-D)
    attn_kernel<<<dim3(16, 32), 256>>>();

    // 5. output projection (bf16x3 tensor cores)
    gemm_bf16x3<1><<<dim3(8, 32), 256>>>(gy_dev, Wo, nullptr, nullptr, out);
}

// round 3
// speedup vs baseline: 3.5805x; 3.5805x over previous
#include <cuda_runtime.h>
#include <cuda_bf16.h>
#include <cstdint>

// ---------------------------------------------------------------------------
// GQA: B=2, T=2048, C=1024, H=16 q-heads, KVH=4 kv-heads, D=64, causal, RoPE
// ---------------------------------------------------------------------------

__device__ __align__(16) float g_q[4194304];
__device__ __align__(16) float g_k[1048576];
__device__ __align__(16) float g_v[1048576];
__device__ __align__(16) float g_y[4194304];

// ---------------------------------------------------------------------------
// mma / ldmatrix helpers
// ---------------------------------------------------------------------------
__device__ __forceinline__ uint32_t smem_u32(const void* p) {
    return (uint32_t)__cvta_generic_to_shared(p);
}
__device__ __forceinline__ void ldmx4(uint32_t* r, uint32_t addr) {
    asm volatile("ldmatrix.sync.aligned.m8n8.x4.shared.b16 {%0,%1,%2,%3}, [%4];"
        : "=r"(r[0]), "=r"(r[1]), "=r"(r[2]), "=r"(r[3]) : "r"(addr));
}
__device__ __forceinline__ void ldmx4t(uint32_t* r, uint32_t addr) {
    asm volatile("ldmatrix.sync.aligned.m8n8.x4.trans.shared.b16 {%0,%1,%2,%3}, [%4];"
        : "=r"(r[0]), "=r"(r[1]), "=r"(r[2]), "=r"(r[3]) : "r"(addr));
}
__device__ __forceinline__ void mma_bf16(float* c, const uint32_t* a, const uint32_t* b) {
    asm volatile(
        "mma.sync.aligned.m16n8k16.row.col.f32.bf16.bf16.f32 "
        "{%0,%1,%2,%3}, {%4,%5,%6,%7}, {%8,%9}, {%0,%1,%2,%3};\n"
        : "+f"(c[0]), "+f"(c[1]), "+f"(c[2]), "+f"(c[3])
        : "r"(a[0]), "r"(a[1]), "r"(a[2]), "r"(a[3]), "r"(b[0]), "r"(b[1]));
}
__device__ __forceinline__ float ex2(float x) {
    float r;
    asm("ex2.approx.f32 %0, %1;" : "=f"(r) : "f"(x));
    return r;
}
// pack two floats into bf16x2 hi and lo (residual) words
__device__ __forceinline__ void pack_hl(float x, float y, uint32_t& h, uint32_t& l) {
    __nv_bfloat162 hb, lb;
    __nv_bfloat16 hx = __float2bfloat16(x);
    hb.x = hx; lb.x = __float2bfloat16(x - __bfloat162float(hx));
    __nv_bfloat16 hy = __float2bfloat16(y);
    hb.y = hy; lb.y = __float2bfloat16(y - __bfloat162float(hy));
    h = *(uint32_t*)&hb; l = *(uint32_t*)&lb;
}

// split a float4 into hi/lo bf16 pairs and store to two smem arrays
__device__ __forceinline__ void split_store(__nv_bfloat16* sh, __nv_bfloat16* sl,
                                            int off, float4 v) {
    __nv_bfloat162 h2, l2;
    __nv_bfloat16 h;
    h = __float2bfloat16(v.x); h2.x = h; l2.x = __float2bfloat16(v.x - __bfloat162float(h));
    h = __float2bfloat16(v.y); h2.y = h; l2.y = __float2bfloat16(v.y - __bfloat162float(h));
    *(__nv_bfloat162*)(sh + off)     = h2;
    *(__nv_bfloat162*)(sl + off)     = l2;
    h = __float2bfloat16(v.z); h2.x = h; l2.x = __float2bfloat16(v.z - __bfloat162float(h));
    h = __float2bfloat16(v.w); h2.y = h; l2.y = __float2bfloat16(v.w - __bfloat162float(h));
    *(__nv_bfloat162*)(sh + off + 2) = h2;
    *(__nv_bfloat162*)(sl + off + 2) = l2;
}

__device__ __forceinline__ void qkv_scatter(int r, int c, float v0, float v1) {
    int b = r >> 11, t = r & 2047;
    float2 v; v.x = v0; v.y = v1;
    if (c < 1024) {
        int h = c >> 6, d = c & 63;
        *(float2*)&g_q[(((b * 16 + h) * 2048 + t) << 6) + d] = v;
    } else if (c < 1280) {
        int c2 = c - 1024; int h = c2 >> 6, d = c2 & 63;
        *(float2*)&g_k[(((b * 4 + h) * 2048 + t) << 6) + d] = v;
    } else {
        int c2 = c - 1280; int h = c2 >> 6, d = c2 & 63;
        *(float2*)&g_v[(((b * 4 + h) * 2048 + t) << 6) + d] = v;
    }
}

// ---------------------------------------------------------------------------
// bf16x3 GEMM (fp32-accurate via hi/lo split, HMMA tensor path).
// (unchanged from R2 — measured ~170us for both GEMMs combined)
// ---------------------------------------------------------------------------
template<int MODE>
__global__ void __launch_bounds__(256, 1) gemm_bf16x3(
    const float* __restrict__ A,
    const float* __restrict__ B0,
    const float* __restrict__ B1,
    const float* __restrict__ B2,
    float* __restrict__ Cout)
{
    __shared__ __align__(16) __nv_bfloat16 sAh[128 * 40];
    __shared__ __align__(16) __nv_bfloat16 sAl[128 * 40];
    __shared__ __align__(16) __nv_bfloat16 sBh[32 * 136];
    __shared__ __align__(16) __nv_bfloat16 sBl[32 * 136];

    int tid  = threadIdx.x;
    int lane = tid & 31;
    int warp = tid >> 5;
    int wm   = warp >> 1;
    int wn   = warp & 1;
    int brow = blockIdx.y * 128;
    int bcol = blockIdx.x * 128;

    const float* Bmat; int ldb, bc0;
    if (MODE == 1) { Bmat = B0; ldb = 1024; bc0 = bcol; }
    else {
        if (bcol < 1024)      { Bmat = B0; ldb = 1024; bc0 = bcol;        }
        else if (bcol < 1280) { Bmat = B1; ldb = 256;  bc0 = bcol - 1024; }
        else                  { Bmat = B2; ldb = 256;  bc0 = bcol - 1280; }
    }

    float c[2][8][4];
    #pragma unroll
    for (int mt = 0; mt < 2; mt++)
        #pragma unroll
        for (int nt = 0; nt < 8; nt++)
            #pragma unroll
            for (int i = 0; i < 4; i++) c[mt][nt][i] = 0.f;

    float4 pa[4], pb[4];
    #pragma unroll
    for (int i = 0; i < 4; i++) {
        int f = tid + i * 256;
        pa[i] = *(const float4*)(A + (brow + (f >> 3)) * 1024 + ((f & 7) << 2));
        pb[i] = *(const float4*)(Bmat + (f >> 5) * ldb + bc0 + ((f & 31) << 2));
    }

    uint32_t aHb = smem_u32(sAh), aLb = smem_u32(sAl);
    uint32_t bHb = smem_u32(sBh), bLb = smem_u32(sBl);

    for (int kb = 0; kb < 1024; kb += 32) {
        __syncthreads();
        #pragma unroll
        for (int i = 0; i < 4; i++) {
            int f = tid + i * 256;
            split_store(sAh, sAl, (f >> 3) * 40 + ((f & 7) << 2), pa[i]);
            split_store(sBh, sBl, (f >> 5) * 136 + ((f & 31) << 2), pb[i]);
        }
        __syncthreads();

        if (kb + 32 < 1024) {
            #pragma unroll
            for (int i = 0; i < 4; i++) {
                int f = tid + i * 256;
                pa[i] = *(const float4*)(A + (brow + (f >> 3)) * 1024 + kb + 32 + ((f & 7) << 2));
                pb[i] = *(const float4*)(Bmat + (kb + 32 + (f >> 5)) * ldb + bc0 + ((f & 31) << 2));
            }
        }

        #pragma unroll
        for (int ks = 0; ks < 2; ks++) {
            uint32_t aH[2][4], aL[2][4], bH[4][4], bL[4][4];
            #pragma unroll
            for (int mt = 0; mt < 2; mt++) {
                uint32_t off = 2u * ((uint32_t)(wm * 32 + mt * 16 + (lane & 15)) * 40
                                     + ks * 16 + ((lane >> 4) << 3));
                ldmx4(aH[mt], aHb + off);
                ldmx4(aL[mt], aLb + off);
            }
            #pragma unroll
            for (int np = 0; np < 4; np++) {
                uint32_t off = 2u * ((uint32_t)(ks * 16 + (lane & 15)) * 136
                                     + wn * 64 + np * 16 + ((lane >> 4) << 3));
                ldmx4t(bH[np], bHb + off);
                ldmx4t(bL[np], bLb + off);
            }
            #pragma unroll
            for (int mt = 0; mt < 2; mt++)
                #pragma unroll
                for (int nt = 0; nt < 8; nt++) {
                    const uint32_t* bh = &bH[nt >> 1][(nt & 1) * 2];
                    const uint32_t* bl = &bL[nt >> 1][(nt & 1) * 2];
                    mma_bf16(c[mt][nt], aH[mt], bh);
                    mma_bf16(c[mt][nt], aH[mt], bl);
                    mma_bf16(c[mt][nt], aL[mt], bh);
                }
        }
    }

    #pragma unroll
    for (int mt = 0; mt < 2; mt++) {
        int r0 = brow + wm * 32 + mt * 16 + (lane >> 2);
        #pragma unroll
        for (int nt = 0; nt < 8; nt++) {
            int cc = bcol + wn * 64 + nt * 8 + ((lane & 3) << 1);
            if (MODE == 1) {
                float2 v0; v0.x = c[mt][nt][0]; v0.y = c[mt][nt][1];
                float2 v1; v1.x = c[mt][nt][2]; v1.y = c[mt][nt][3];
                *(float2*)(Cout + r0 * 1024 + cc)       = v0;
                *(float2*)(Cout + (r0 + 8) * 1024 + cc) = v1;
            } else {
                qkv_scatter(r0,     cc, c[mt][nt][0], c[mt][nt][1]);
                qkv_scatter(r0 + 8, cc, c[mt][nt][2], c[mt][nt][3]);
            }
        }
    }
}

// ---------------------------------------------------------------------------
// In-place RoPE on g_q (which=0) or g_k (which=1).
// ---------------------------------------------------------------------------
__global__ void rope_kernel(const float* __restrict__ cosb,
                            const float* __restrict__ sinb,
                            int n, int which)
{
    int i = blockIdx.x * blockDim.x + threadIdx.x;
    if (i >= n) return;
    float* buf = which ? g_k : g_q;
    int d  = i & 31;
    int t  = (i >> 5) & 2047;
    int bh = i >> 16;
    float* base = buf + ((bh * 2048 + t) << 6);
    float c = cosb[t * 32 + d];
    float s = sinb[t * 32 + d];
    float x1 = base[d], x2 = base[d + 32];
    base[d]      = x1 * c - x2 * s;
    base[d + 32] = x2 * c + x1 * s;
}

// ---------------------------------------------------------------------------
// MMA flash attention (bf16x3, fp32 accumulate).
// Block = 256 (8 warps). Each warp owns 16 q rows -> CTA covers 128 rows.
// K/V tiles: 64 keys x 64 dims, staged in smem as bf16 hi/lo, pitch 72 halves.
// grid = (T/128 = 16, B*H = 32).
// Scores are computed in log2-domain (1/8 * log2(e) folded into Q) so softmax
// uses ex2.approx only.
// ---------------------------------------------------------------------------
__global__ void __launch_bounds__(256, 1) attn_kernel()
{
    __shared__ __align__(16) __nv_bfloat16 Kh[64 * 72];
    __shared__ __align__(16) __nv_bfloat16 Kl[64 * 72];
    __shared__ __align__(16) __nv_bfloat16 Vh[64 * 72];
    __shared__ __align__(16) __nv_bfloat16 Vl[64 * 72];

    const int tid  = threadIdx.x;
    const int lane = tid & 31;
    const int warp = tid >> 5;
    const int g    = lane >> 2;     // 0..7
    const int t4   = lane & 3;      // 0..3
    const int bh   = blockIdx.y;
    const int b    = bh >> 4, hh = bh & 15;
    const int kh   = hh >> 2;
    const int qt   = blockIdx.x;

    const int r0 = qt * 128 + warp * 16 + g;   // first q row of this thread
    const int r1 = r0 + 8;
    const int warp_max_row = qt * 128 + warp * 16 + 15;

    // ---- load Q fragments (hi/lo), scale = 1/8 * log2(e) folded in ----
    const float SC = 0.125f * 1.44269504088896f;
    uint32_t qh[4][4], ql[4][4];
    {
        const float* q0 = g_q + ((bh * 2048 + r0) << 6);
        const float* q1 = g_q + ((bh * 2048 + r1) << 6);
        #pragma unroll
        for (int ks = 0; ks < 4; ks++) {
            float2 v00 = *(const float2*)(q0 + 16 * ks + 2 * t4);
            float2 v10 = *(const float2*)(q1 + 16 * ks + 2 * t4);
            float2 v01 = *(const float2*)(q0 + 16 * ks + 8 + 2 * t4);
            float2 v11 = *(const float2*)(q1 + 16 * ks + 8 + 2 * t4);
            pack_hl(v00.x * SC, v00.y * SC, qh[ks][0], ql[ks][0]);
            pack_hl(v10.x * SC, v10.y * SC, qh[ks][1], ql[ks][1]);
            pack_hl(v01.x * SC, v01.y * SC, qh[ks][2], ql[ks][2]);
            pack_hl(v11.x * SC, v11.y * SC, qh[ks][3], ql[ks][3]);
        }
    }

    float o[8][4];
    #pragma unroll
    for (int nt = 0; nt < 8; nt++)
        #pragma unroll
        for (int i = 0; i < 4; i++) o[nt][i] = 0.f;
    float m0 = -1e30f, m1 = -1e30f, l0 = 0.f, l1 = 0.f;

    const float4* kbase = (const float4*)(g_k + (((b * 4 + kh) * 2048) << 6));
    const float4* vbase = (const float4*)(g_v + (((b * 4 + kh) * 2048) << 6));

    const uint32_t bKh = smem_u32(Kh), bKl = smem_u32(Kl);
    const uint32_t bVh = smem_u32(Vh), bVl = smem_u32(Vl);

    const int ntiles = 2 * qt + 2;
    for (int kt = 0; kt < ntiles; kt++) {
        __syncthreads();
        // stage K/V tile (fp32 -> bf16 hi/lo), 4096 floats each
        #pragma unroll
        for (int i = 0; i < 4; i++) {
            int f4  = tid + i * 256;            // 0..1023 float4
            int row = f4 >> 4;
            int c4  = (f4 & 15) << 2;
            split_store(Kh, Kl, row * 72 + c4, kbase[kt * 1024 + f4]);
            split_store(Vh, Vl, row * 72 + c4, vbase[kt * 1024 + f4]);
        }
        __syncthreads();

        if (kt * 64 > warp_max_row) continue;   // tile fully masked for warp

        // ---- S = Q K^T (bf16x3) ----
        float s[8][4];
        #pragma unroll
        for (int nt = 0; nt < 8; nt++)
            #pragma unroll
            for (int i = 0; i < 4; i++) s[nt][i] = 0.f;

        #pragma unroll
        for (int ks = 0; ks < 4; ks++) {
            uint32_t kbh[4][4], kbl[4][4];
            #pragma unroll
            for (int pr = 0; pr < 4; pr++) {
                int n_idx = pr * 16 + (lane & 7) + ((lane >> 4) << 3);
                int koff  = 16 * ks + ((lane >> 3) & 1) * 8;
                uint32_t off = 2u * (uint32_t)(n_idx * 72 + koff);
                ldmx4(kbh[pr], bKh + off);
                ldmx4(kbl[pr], bKl + off);
            }
            #pragma unroll
            for (int pr = 0; pr < 4; pr++)
                #pragma unroll
                for (int sub = 0; sub < 2; sub++) {
                    float* sc = s[pr * 2 + sub];
                    mma_bf16(sc, qh[ks], &kbh[pr][sub * 2]);
                    mma_bf16(sc, qh[ks], &kbl[pr][sub * 2]);
                    mma_bf16(sc, ql[ks], &kbh[pr][sub * 2]);
                }
        }

        // ---- causal mask (only diagonal tiles) ----
        if (kt * 64 + 63 > qt * 128 + warp * 16) {
            #pragma unroll
            for (int nt = 0; nt < 8; nt++) {
                int c0 = kt * 64 + nt * 8 + 2 * t4;
                if (c0     > r0) s[nt][0] = -1e30f;
                if (c0 + 1 > r0) s[nt][1] = -1e30f;
                if (c0     > r1) s[nt][2] = -1e30f;
                if (c0 + 1 > r1) s[nt][3] = -1e30f;
            }
        }

        // ---- online softmax (log2 domain) ----
        float t0 = -1e30f, t1 = -1e30f;
        #pragma unroll
        for (int nt = 0; nt < 8; nt++) {
            t0 = fmaxf(t0, fmaxf(s[nt][0], s[nt][1]));
            t1 = fmaxf(t1, fmaxf(s[nt][2], s[nt][3]));
        }
        t0 = fmaxf(t0, __shfl_xor_sync(0xffffffffu, t0, 1));
        t0 = fmaxf(t0, __shfl_xor_sync(0xffffffffu, t0, 2));
        t1 = fmaxf(t1, __shfl_xor_sync(0xffffffffu, t1, 1));
        t1 = fmaxf(t1, __shfl_xor_sync(0xffffffffu, t1, 2));

        float m0n = fmaxf(m0, t0), m1n = fmaxf(m1, t1);
        float c0f = ex2(m0 - m0n), c1f = ex2(m1 - m1n);
        m0 = m0n; m1 = m1n;

        float sum0 = 0.f, sum1 = 0.f;
        #pragma unroll
        for (int nt = 0; nt < 8; nt++) {
            float p0 = ex2(s[nt][0] - m0);
            float p1 = ex2(s[nt][1] - m0);
            float p2 = ex2(s[nt][2] - m1);
            float p3 = ex2(s[nt][3] - m1);
            sum0 += p0 + p1; sum1 += p2 + p3;
            s[nt][0] = p0; s[nt][1] = p1; s[nt][2] = p2; s[nt][3] = p3;
        }
        l0 = l0 * c0f + sum0;
        l1 = l1 * c1f + sum1;
        #pragma unroll
        for (int nt = 0; nt < 8; nt++) {
            o[nt][0] *= c0f; o[nt][1] *= c0f;
            o[nt][2] *= c1f; o[nt][3] *= c1f;
        }

        // ---- O += P V (bf16x3) ----
        #pragma unroll
        for (int ks = 0; ks < 4; ks++) {
            uint32_t aPh[4], aPl[4];
            pack_hl(s[2*ks][0],   s[2*ks][1],   aPh[0], aPl[0]);
            pack_hl(s[2*ks][2],   s[2*ks][3],   aPh[1], aPl[1]);
            pack_hl(s[2*ks+1][0], s[2*ks+1][1], aPh[2], aPl[2]);
            pack_hl(s[2*ks+1][2], s[2*ks+1][3], aPh[3], aPl[3]);

            #pragma unroll
            for (int dp = 0; dp < 4; dp++) {
                uint32_t vfh[4], vfl[4];
                uint32_t off = 2u * (uint32_t)((16 * ks + (lane & 15)) * 72
                                               + dp * 16 + ((lane >> 4) << 3));
                ldmx4t(vfh, bVh + off);
                ldmx4t(vfl, bVl + off);
                #pragma unroll
                for (int sub = 0; sub < 2; sub++) {
                    float* oc = o[dp * 2 + sub];
                    mma_bf16(oc, aPh, &vfh[sub * 2]);
                    mma_bf16(oc, aPh, &vfl[sub * 2]);
                    mma_bf16(oc, aPl, &vfh[sub * 2]);
                }
            }
        }
    }

    // ---- epilogue ----
    l0 += __shfl_xor_sync(0xffffffffu, l0, 1);
    l0 += __shfl_xor_sync(0xffffffffu, l0, 2);
    l1 += __shfl_xor_sync(0xffffffffu, l1, 1);
    l1 += __shfl_xor_sync(0xffffffffu, l1, 2);
    float inv0 = 1.f / l0, inv1 = 1.f / l1;

    float* y0 = g_y + (b * 2048 + r0) * 1024 + hh * 64;
    float* y1 = g_y + (b * 2048 + r1) * 1024 + hh * 64;
    #pragma unroll
    for (int nt = 0; nt < 8; nt++) {
        float2 w0; w0.x = o[nt][0] * inv0; w0.y = o[nt][1] * inv0;
        float2 w1; w1.x = o[nt][2] * inv1; w1.y = o[nt][3] * inv1;
        *(float2*)(y0 + nt * 8 + 2 * t4) = w0;
        *(float2*)(y1 + nt * 8 + 2 * t4) = w1;
    }
}

// ---------------------------------------------------------------------------
// Launch: x, cos, sin, Wq, Wk, Wv, Wo. out = f32 [B,T,C].
// ---------------------------------------------------------------------------
extern "C" void kernel_launch(void* const* d_in, const int* in_sizes, int n_in,
                              void* d_out, int out_size)
{
    const float* x    = (const float*)d_in[0];
    const float* cosb = (const float*)d_in[1];
    const float* sinb = (const float*)d_in[2];
    const float* Wq   = (const float*)d_in[3];
    const float* Wk   = (const float*)d_in[4];
    const float* Wv   = (const float*)d_in[5];
    const float* Wo   = (const float*)d_in[6];
    float* out = (float*)d_out;

    float* gy_dev = nullptr;
    cudaGetSymbolAddress((void**)&gy_dev, g_y);

    gemm_bf16x3<0><<<dim3(12, 32), 256>>>(x, Wq, Wk, Wv, nullptr);
    rope_kernel<<<8192, 256>>>(cosb, sinb, 2097152, 0);
    rope_kernel<<<2048, 256>>>(cosb, sinb, 524288, 1);
    attn_kernel<<<dim3(16, 32), 256>>>();
    gemm_bf16x3<1><<<dim3(8, 32), 256>>>(gy_dev, Wo, nullptr, nullptr, out);
}

// round 4
// speedup vs baseline: 3.7492x; 1.0471x over previous
#include <cuda_runtime.h>
#include <cuda_bf16.h>
#include <cstdint>

// ---------------------------------------------------------------------------
// GQA: B=2, T=2048, C=1024, H=16 q-heads, KVH=4 kv-heads, D=64, causal, RoPE
// Q/K/V stored as bf16 hi/lo pairs (split-precision), RoPE+scale fused into
// the QKV GEMM epilogue. y stays fp32 for the Wo GEMM.
// ---------------------------------------------------------------------------

__device__ __align__(16) __nv_bfloat16 g_qh[4194304];
__device__ __align__(16) __nv_bfloat16 g_ql[4194304];
__device__ __align__(16) __nv_bfloat16 g_kh[1048576];
__device__ __align__(16) __nv_bfloat16 g_kl[1048576];
__device__ __align__(16) __nv_bfloat16 g_vh[1048576];
__device__ __align__(16) __nv_bfloat16 g_vl[1048576];
__device__ __align__(16) float g_y[4194304];

// ---------------------------------------------------------------------------
// helpers
// ---------------------------------------------------------------------------
__device__ __forceinline__ uint32_t smem_u32(const void* p) {
    return (uint32_t)__cvta_generic_to_shared(p);
}
__device__ __forceinline__ void ldmx4(uint32_t* r, uint32_t addr) {
    asm volatile("ldmatrix.sync.aligned.m8n8.x4.shared.b16 {%0,%1,%2,%3}, [%4];"
        : "=r"(r[0]), "=r"(r[1]), "=r"(r[2]), "=r"(r[3]) : "r"(addr));
}
__device__ __forceinline__ void ldmx4t(uint32_t* r, uint32_t addr) {
    asm volatile("ldmatrix.sync.aligned.m8n8.x4.trans.shared.b16 {%0,%1,%2,%3}, [%4];"
        : "=r"(r[0]), "=r"(r[1]), "=r"(r[2]), "=r"(r[3]) : "r"(addr));
}
__device__ __forceinline__ void mma_bf16(float* c, const uint32_t* a, const uint32_t* b) {
    asm volatile(
        "mma.sync.aligned.m16n8k16.row.col.f32.bf16.bf16.f32 "
        "{%0,%1,%2,%3}, {%4,%5,%6,%7}, {%8,%9}, {%0,%1,%2,%3};\n"
        : "+f"(c[0]), "+f"(c[1]), "+f"(c[2]), "+f"(c[3])
        : "r"(a[0]), "r"(a[1]), "r"(a[2]), "r"(a[3]), "r"(b[0]), "r"(b[1]));
}
__device__ __forceinline__ float ex2(float x) {
    float r;
    asm("ex2.approx.f32 %0, %1;" : "=f"(r) : "f"(x));
    return r;
}
__device__ __forceinline__ void pack_hl(float x, float y, uint32_t& h, uint32_t& l) {
    __nv_bfloat162 hb, lb;
    __nv_bfloat16 hx = __float2bfloat16(x);
    hb.x = hx; lb.x = __float2bfloat16(x - __bfloat162float(hx));
    __nv_bfloat16 hy = __float2bfloat16(y);
    hb.y = hy; lb.y = __float2bfloat16(y - __bfloat162float(hy));
    h = *(uint32_t*)&hb; l = *(uint32_t*)&lb;
}
__device__ __forceinline__ void store_hl(__nv_bfloat16* H, __nv_bfloat16* L,
                                         int idx, float a, float b) {
    uint32_t h, l; pack_hl(a, b, h, l);
    *(uint32_t*)(H + idx) = h;
    *(uint32_t*)(L + idx) = l;
}
__device__ __forceinline__ void split_store(__nv_bfloat16* sh, __nv_bfloat16* sl,
                                            int off, float4 v) {
    __nv_bfloat162 h2, l2;
    __nv_bfloat16 h;
    h = __float2bfloat16(v.x); h2.x = h; l2.x = __float2bfloat16(v.x - __bfloat162float(h));
    h = __float2bfloat16(v.y); h2.y = h; l2.y = __float2bfloat16(v.y - __bfloat162float(h));
    *(__nv_bfloat162*)(sh + off)     = h2;
    *(__nv_bfloat162*)(sl + off)     = l2;
    h = __float2bfloat16(v.z); h2.x = h; l2.x = __float2bfloat16(v.z - __bfloat162float(h));
    h = __float2bfloat16(v.w); h2.y = h; l2.y = __float2bfloat16(v.w - __bfloat162float(h));
    *(__nv_bfloat162*)(sh + off + 2) = h2;
    *(__nv_bfloat162*)(sl + off + 2) = l2;
}
__device__ __forceinline__ void cpa16(uint32_t dst, const void* src) {
    asm volatile("cp.async.cg.shared.global [%0], [%1], 16;\n" :: "r"(dst), "l"(src));
}

#define SOFTMAX_SCALE (0.125f * 1.44269504088896f)  // 1/sqrt(64) * log2(e)

// ---------------------------------------------------------------------------
// bf16x3 GEMM (fp32-accurate via hi/lo split, HMMA).
// MODE 0: A=x, B=[Wq|Wk|Wv]; epilogue applies RoPE (+softmax scale on Q) in
//         registers and stores bf16 hi/lo into g_{q,k,v}{h,l}.
// MODE 1: A=g_y (fp32), B=Wo; plain fp32 epilogue into Cout.
// ---------------------------------------------------------------------------
template<int MODE>
__global__ void __launch_bounds__(256, 1) gemm_bf16x3(
    const float* __restrict__ A,
    const float* __restrict__ B0,
    const float* __restrict__ B1,
    const float* __restrict__ B2,
    const float* __restrict__ cosb,
    const float* __restrict__ sinb,
    float* __restrict__ Cout)
{
    __shared__ __align__(16) __nv_bfloat16 sAh[128 * 40];
    __shared__ __align__(16) __nv_bfloat16 sAl[128 * 40];
    __shared__ __align__(16) __nv_bfloat16 sBh[32 * 136];
    __shared__ __align__(16) __nv_bfloat16 sBl[32 * 136];

    int tid  = threadIdx.x;
    int lane = tid & 31;
    int warp = tid >> 5;
    int wm   = warp >> 1;
    int wn   = warp & 1;
    int brow = blockIdx.y * 128;
    int bcol = blockIdx.x * 128;
    int t4   = lane & 3;

    const float* Bmat; int ldb, bc0;
    if (MODE == 1) { Bmat = B0; ldb = 1024; bc0 = bcol; }
    else {
        if (bcol < 1024)      { Bmat = B0; ldb = 1024; bc0 = bcol;        }
        else if (bcol < 1280) { Bmat = B1; ldb = 256;  bc0 = bcol - 1024; }
        else                  { Bmat = B2; ldb = 256;  bc0 = bcol - 1280; }
    }

    float c[2][8][4];
    #pragma unroll
    for (int mt = 0; mt < 2; mt++)
        #pragma unroll
        for (int nt = 0; nt < 8; nt++)
            #pragma unroll
            for (int i = 0; i < 4; i++) c[mt][nt][i] = 0.f;

    float4 pa[4], pb[4];
    #pragma unroll
    for (int i = 0; i < 4; i++) {
        int f = tid + i * 256;
        pa[i] = *(const float4*)(A + (brow + (f >> 3)) * 1024 + ((f & 7) << 2));
        pb[i] = *(const float4*)(Bmat + (f >> 5) * ldb + bc0 + ((f & 31) << 2));
    }

    uint32_t aHb = smem_u32(sAh), aLb = smem_u32(sAl);
    uint32_t bHb = smem_u32(sBh), bLb = smem_u32(sBl);

    for (int kb = 0; kb < 1024; kb += 32) {
        __syncthreads();
        #pragma unroll
        for (int i = 0; i < 4; i++) {
            int f = tid + i * 256;
            split_store(sAh, sAl, (f >> 3) * 40 + ((f & 7) << 2), pa[i]);
            split_store(sBh, sBl, (f >> 5) * 136 + ((f & 31) << 2), pb[i]);
        }
        __syncthreads();

        if (kb + 32 < 1024) {
            #pragma unroll
            for (int i = 0; i < 4; i++) {
                int f = tid + i * 256;
                pa[i] = *(const float4*)(A + (brow + (f >> 3)) * 1024 + kb + 32 + ((f & 7) << 2));
                pb[i] = *(const float4*)(Bmat + (kb + 32 + (f >> 5)) * ldb + bc0 + ((f & 31) << 2));
            }
        }

        #pragma unroll
        for (int ks = 0; ks < 2; ks++) {
            uint32_t aH[2][4], aL[2][4], bH[4][4], bL[4][4];
            #pragma unroll
            for (int mt = 0; mt < 2; mt++) {
                uint32_t off = 2u * ((uint32_t)(wm * 32 + mt * 16 + (lane & 15)) * 40
                                     + ks * 16 + ((lane >> 4) << 3));
                ldmx4(aH[mt], aHb + off);
                ldmx4(aL[mt], aLb + off);
            }
            #pragma unroll
            for (int np = 0; np < 4; np++) {
                uint32_t off = 2u * ((uint32_t)(ks * 16 + (lane & 15)) * 136
                                     + wn * 64 + np * 16 + ((lane >> 4) << 3));
                ldmx4t(bH[np], bHb + off);
                ldmx4t(bL[np], bLb + off);
            }
            #pragma unroll
            for (int mt = 0; mt < 2; mt++)
                #pragma unroll
                for (int nt = 0; nt < 8; nt++) {
                    const uint32_t* bh = &bH[nt >> 1][(nt & 1) * 2];
                    const uint32_t* bl = &bL[nt >> 1][(nt & 1) * 2];
                    mma_bf16(c[mt][nt], aH[mt], bh);
                    mma_bf16(c[mt][nt], aH[mt], bl);
                    mma_bf16(c[mt][nt], aL[mt], bh);
                }
        }
    }

    if (MODE == 1) {
        #pragma unroll
        for (int mt = 0; mt < 2; mt++) {
            int r0 = brow + wm * 32 + mt * 16 + (lane >> 2);
            #pragma unroll
            for (int nt = 0; nt < 8; nt++) {
                int cc = bcol + wn * 64 + nt * 8 + (t4 << 1);
                float2 v0; v0.x = c[mt][nt][0]; v0.y = c[mt][nt][1];
                float2 v1; v1.x = c[mt][nt][2]; v1.y = c[mt][nt][3];
                *(float2*)(Cout + r0 * 1024 + cc)       = v0;
                *(float2*)(Cout + (r0 + 8) * 1024 + cc) = v1;
            }
        }
    } else {
        // region is uniform per block (regions are 128-aligned in N)
        int region = (bcol < 1024) ? 0 : (bcol < 1280 ? 1 : 2);
        #pragma unroll
        for (int mt = 0; mt < 2; mt++) {
            int r0 = brow + wm * 32 + mt * 16 + (lane >> 2);
            int r1 = r0 + 8;
            int b0 = r0 >> 11, t0 = r0 & 2047;
            int b1 = r1 >> 11, t1 = r1 & 2047;
            if (region == 2) {
                int colb = bcol - 1280 + wn * 64;
                int h = colb >> 6;
                #pragma unroll
                for (int nt = 0; nt < 8; nt++) {
                    int d = nt * 8 + (t4 << 1);
                    int i0 = ((b0 * 4 + h) * 2048 + t0) * 64 + d;
                    int i1 = ((b1 * 4 + h) * 2048 + t1) * 64 + d;
                    store_hl(g_vh, g_vl, i0, c[mt][nt][0], c[mt][nt][1]);
                    store_hl(g_vh, g_vl, i1, c[mt][nt][2], c[mt][nt][3]);
                }
            } else {
                int colb = (region == 0) ? bcol + wn * 64 : bcol - 1024 + wn * 64;
                int h = colb >> 6;
                __nv_bfloat16* H = (region == 0) ? g_qh : g_kh;
                __nv_bfloat16* L = (region == 0) ? g_ql : g_kl;
                int nh   = (region == 0) ? 16 : 4;
                float sc = (region == 0) ? SOFTMAX_SCALE : 1.f;
                #pragma unroll
                for (int nt = 0; nt < 4; nt++) {
                    int d = nt * 8 + (t4 << 1);          // < 32
                    float2 cc0 = *(const float2*)(cosb + t0 * 32 + d);
                    float2 ss0 = *(const float2*)(sinb + t0 * 32 + d);
                    float2 cc1 = *(const float2*)(cosb + t1 * 32 + d);
                    float2 ss1 = *(const float2*)(sinb + t1 * 32 + d);
                    // row r0
                    float x1a = c[mt][nt][0],     x1b = c[mt][nt][1];
                    float x2a = c[mt][nt + 4][0], x2b = c[mt][nt + 4][1];
                    int i0 = ((b0 * nh + h) * 2048 + t0) * 64 + d;
                    store_hl(H, L, i0,      (x1a*cc0.x - x2a*ss0.x)*sc, (x1b*cc0.y - x2b*ss0.y)*sc);
                    store_hl(H, L, i0 + 32, (x2a*cc0.x + x1a*ss0.x)*sc, (x2b*cc0.y + x1b*ss0.y)*sc);
                    // row r1
                    x1a = c[mt][nt][2];     x1b = c[mt][nt][3];
                    x2a = c[mt][nt + 4][2]; x2b = c[mt][nt + 4][3];
                    int i1 = ((b1 * nh + h) * 2048 + t1) * 64 + d;
                    store_hl(H, L, i1,      (x1a*cc1.x - x2a*ss1.x)*sc, (x1b*cc1.y - x2b*ss1.y)*sc);
                    store_hl(H, L, i1 + 32, (x2a*cc1.x + x1a*ss1.x)*sc, (x2b*cc1.y + x1b*ss1.y)*sc);
                }
            }
        }
    }
}

// ---------------------------------------------------------------------------
// MMA flash attention (bf16x3, fp32 accumulate), pre-split K/V, cp.async
// double-buffered K/V staging.
// Block = 256 (8 warps), each warp 16 q rows -> CTA = 128 rows.
// K/V tiles: 64 keys x 64 dims, smem pitch 72 halves.
// Dynamic smem: 2 bufs x 4 arrays (Kh,Kl,Vh,Vl) x 4608 halves = 73,728 B.
// grid = (16, 32).
// ---------------------------------------------------------------------------
__global__ void __launch_bounds__(256, 1) attn_kernel()
{
    extern __shared__ __align__(16) __nv_bfloat16 smem[];
    const uint32_t sbase = smem_u32(smem);

    const int tid  = threadIdx.x;
    const int lane = tid & 31;
    const int warp = tid >> 5;
    const int g    = lane >> 2;
    const int t4   = lane & 3;
    const int bh   = blockIdx.y;
    const int b    = bh >> 4, hh = bh & 15;
    const int kh   = hh >> 2;
    const int qt   = blockIdx.x;

    const int r0 = qt * 128 + warp * 16 + g;
    const int r1 = r0 + 8;
    const int warp_max_row = qt * 128 + warp * 16 + 15;

    // ---- Q fragments: direct uint32 loads (scale already folded in) ----
    uint32_t qh[4][4], ql[4][4];
    {
        const __nv_bfloat16* q0h = g_qh + (bh * 2048 + r0) * 64;
        const __nv_bfloat16* q1h = g_qh + (bh * 2048 + r1) * 64;
        const __nv_bfloat16* q0l = g_ql + (bh * 2048 + r0) * 64;
        const __nv_bfloat16* q1l = g_ql + (bh * 2048 + r1) * 64;
        #pragma unroll
        for (int ks = 0; ks < 4; ks++) {
            int cb = ks * 16 + (t4 << 1);
            qh[ks][0] = *(const uint32_t*)(q0h + cb);
            qh[ks][1] = *(const uint32_t*)(q1h + cb);
            qh[ks][2] = *(const uint32_t*)(q0h + cb + 8);
            qh[ks][3] = *(const uint32_t*)(q1h + cb + 8);
            ql[ks][0] = *(const uint32_t*)(q0l + cb);
            ql[ks][1] = *(const uint32_t*)(q1l + cb);
            ql[ks][2] = *(const uint32_t*)(q0l + cb + 8);
            ql[ks][3] = *(const uint32_t*)(q1l + cb + 8);
        }
    }

    float o[8][4];
    #pragma unroll
    for (int nt = 0; nt < 8; nt++)
        #pragma unroll
        for (int i = 0; i < 4; i++) o[nt][i] = 0.f;
    float m0 = -1e30f, m1 = -1e30f, l0 = 0.f, l1 = 0.f;

    const __nv_bfloat16* src0 = g_kh + ((b * 4 + kh) * 2048) * 64;
    const __nv_bfloat16* src1 = g_kl + ((b * 4 + kh) * 2048) * 64;
    const __nv_bfloat16* src2 = g_vh + ((b * 4 + kh) * 2048) * 64;
    const __nv_bfloat16* src3 = g_vl + ((b * 4 + kh) * 2048) * 64;

    const int ntiles = 2 * qt + 2;

    // stage a K/V tile via cp.async (all 256 threads, 8x 16B each)
    auto stage = [&](int kt, int buf) {
        const __nv_bfloat16* srcs[4] = {src0, src1, src2, src3};
        #pragma unroll
        for (int a = 0; a < 4; a++) {
            uint32_t dbase = sbase + (uint32_t)(buf * 4 + a) * 9216u;
            const __nv_bfloat16* sp = srcs[a] + kt * 4096;
            #pragma unroll
            for (int i = 0; i < 2; i++) {
                int u = tid + i * 256;
                int row = u >> 3, c8 = (u & 7) << 3;
                cpa16(dbase + (uint32_t)(row * 72 + c8) * 2u, sp + u * 8);
            }
        }
        asm volatile("cp.async.commit_group;\n" ::: "memory");
    };

    stage(0, 0);

    for (int kt = 0; kt < ntiles; kt++) {
        int buf = kt & 1;
        if (kt + 1 < ntiles) {
            stage(kt + 1, buf ^ 1);
            asm volatile("cp.async.wait_group 1;\n" ::: "memory");
        } else {
            asm volatile("cp.async.wait_group 0;\n" ::: "memory");
        }
        __syncthreads();

        if (kt * 64 <= warp_max_row) {
            const uint32_t bKh = sbase + (uint32_t)(buf * 4 + 0) * 9216u;
            const uint32_t bKl = sbase + (uint32_t)(buf * 4 + 1) * 9216u;
            const uint32_t bVh = sbase + (uint32_t)(buf * 4 + 2) * 9216u;
            const uint32_t bVl = sbase + (uint32_t)(buf * 4 + 3) * 9216u;

            // ---- S = Q K^T (bf16x3) ----
            float s[8][4];
            #pragma unroll
            for (int nt = 0; nt < 8; nt++)
                #pragma unroll
                for (int i = 0; i < 4; i++) s[nt][i] = 0.f;

            #pragma unroll
            for (int ks = 0; ks < 4; ks++) {
                uint32_t kbh[4][4], kbl[4][4];
                #pragma unroll
                for (int pr = 0; pr < 4; pr++) {
                    int n_idx = pr * 16 + (lane & 7) + ((lane >> 4) << 3);
                    int koff  = 16 * ks + ((lane >> 3) & 1) * 8;
                    uint32_t off = 2u * (uint32_t)(n_idx * 72 + koff);
                    ldmx4(kbh[pr], bKh + off);
                    ldmx4(kbl[pr], bKl + off);
                }
                #pragma unroll
                for (int pr = 0; pr < 4; pr++)
                    #pragma unroll
                    for (int sub = 0; sub < 2; sub++) {
                        float* sc = s[pr * 2 + sub];
                        mma_bf16(sc, qh[ks], &kbh[pr][sub * 2]);
                        mma_bf16(sc, qh[ks], &kbl[pr][sub * 2]);
                        mma_bf16(sc, ql[ks], &kbh[pr][sub * 2]);
                    }
            }

            // ---- causal mask (diagonal tiles only) ----
            if (kt * 64 + 63 > qt * 128 + warp * 16) {
                #pragma unroll
                for (int nt = 0; nt < 8; nt++) {
                    int c0 = kt * 64 + nt * 8 + (t4 << 1);
                    if (c0     > r0) s[nt][0] = -1e30f;
                    if (c0 + 1 > r0) s[nt][1] = -1e30f;
                    if (c0     > r1) s[nt][2] = -1e30f;
                    if (c0 + 1 > r1) s[nt][3] = -1e30f;
                }
            }

            // ---- online softmax (log2 domain) ----
            float t0 = -1e30f, t1 = -1e30f;
            #pragma unroll
            for (int nt = 0; nt < 8; nt++) {
                t0 = fmaxf(t0, fmaxf(s[nt][0], s[nt][1]));
                t1 = fmaxf(t1, fmaxf(s[nt][2], s[nt][3]));
            }
            t0 = fmaxf(t0, __shfl_xor_sync(0xffffffffu, t0, 1));
            t0 = fmaxf(t0, __shfl_xor_sync(0xffffffffu, t0, 2));
            t1 = fmaxf(t1, __shfl_xor_sync(0xffffffffu, t1, 1));
            t1 = fmaxf(t1, __shfl_xor_sync(0xffffffffu, t1, 2));

            float m0n = fmaxf(m0, t0), m1n = fmaxf(m1, t1);
            float c0f = ex2(m0 - m0n), c1f = ex2(m1 - m1n);
            m0 = m0n; m1 = m1n;

            float sum0 = 0.f, sum1 = 0.f;
            #pragma unroll
            for (int nt = 0; nt < 8; nt++) {
                float p0 = ex2(s[nt][0] - m0);
                float p1 = ex2(s[nt][1] - m0);
                float p2 = ex2(s[nt][2] - m1);
                float p3 = ex2(s[nt][3] - m1);
                sum0 += p0 + p1; sum1 += p2 + p3;
                s[nt][0] = p0; s[nt][1] = p1; s[nt][2] = p2; s[nt][3] = p3;
            }
            l0 = l0 * c0f + sum0;
            l1 = l1 * c1f + sum1;
            #pragma unroll
            for (int nt = 0; nt < 8; nt++) {
                o[nt][0] *= c0f; o[nt][1] *= c0f;
                o[nt][2] *= c1f; o[nt][3] *= c1f;
            }

            // ---- O += P V (bf16x3) ----
            #pragma unroll
            for (int ks = 0; ks < 4; ks++) {
                uint32_t aPh[4], aPl[4];
                pack_hl(s[2*ks][0],   s[2*ks][1],   aPh[0], aPl[0]);
                pack_hl(s[2*ks][2],   s[2*ks][3],   aPh[1], aPl[1]);
                pack_hl(s[2*ks+1][0], s[2*ks+1][1], aPh[2], aPl[2]);
                pack_hl(s[2*ks+1][2], s[2*ks+1][3], aPh[3], aPl[3]);

                #pragma unroll
                for (int dp = 0; dp < 4; dp++) {
                    uint32_t vfh[4], vfl[4];
                    uint32_t off = 2u * (uint32_t)((16 * ks + (lane & 15)) * 72
                                                   + dp * 16 + ((lane >> 4) << 3));
                    ldmx4t(vfh, bVh + off);
                    ldmx4t(vfl, bVl + off);
                    #pragma unroll
                    for (int sub = 0; sub < 2; sub++) {
                        float* oc = o[dp * 2 + sub];
                        mma_bf16(oc, aPh, &vfh[sub * 2]);
                        mma_bf16(oc, aPh, &vfl[sub * 2]);
                        mma_bf16(oc, aPl, &vfh[sub * 2]);
                    }
                }
            }
        }
        __syncthreads();
    }

    // ---- epilogue ----
    l0 += __shfl_xor_sync(0xffffffffu, l0, 1);
    l0 += __shfl_xor_sync(0xffffffffu, l0, 2);
    l1 += __shfl_xor_sync(0xffffffffu, l1, 1);
    l1 += __shfl_xor_sync(0xffffffffu, l1, 2);
    float inv0 = 1.f / l0, inv1 = 1.f / l1;

    float* y0 = g_y + (b * 2048 + r0) * 1024 + hh * 64;
    float* y1 = g_y + (b * 2048 + r1) * 1024 + hh * 64;
    #pragma unroll
    for (int nt = 0; nt < 8; nt++) {
        float2 w0; w0.x = o[nt][0] * inv0; w0.y = o[nt][1] * inv0;
        float2 w1; w1.x = o[nt][2] * inv1; w1.y = o[nt][3] * inv1;
        *(float2*)(y0 + nt * 8 + (t4 << 1)) = w0;
        *(float2*)(y1 + nt * 8 + (t4 << 1)) = w1;
    }
}

// ---------------------------------------------------------------------------
// Launch: x, cos, sin, Wq, Wk, Wv, Wo. out = f32 [B,T,C].
// ---------------------------------------------------------------------------
extern "C" void kernel_launch(void* const* d_in, const int* in_sizes, int n_in,
                              void* d_out, int out_size)
{
    const float* x    = (const float*)d_in[0];
    const float* cosb = (const float*)d_in[1];
    const float* sinb = (const float*)d_in[2];
    const float* Wq   = (const float*)d_in[3];
    const float* Wk   = (const float*)d_in[4];
    const float* Wv   = (const float*)d_in[5];
    const float* Wo   = (const float*)d_in[6];
    float* out = (float*)d_out;

    float* gy_dev = nullptr;
    cudaGetSymbolAddress((void**)&gy_dev, g_y);

    static bool attr_set = false;
    if (!attr_set) {
        cudaFuncSetAttribute(attn_kernel,
                             cudaFuncAttributeMaxDynamicSharedMemorySize, 73728);
        attr_set = true;
    }

    // 1. fused QKV projection + RoPE + scale + bf16 split (tensor cores)
    gemm_bf16x3<0><<<dim3(12, 32), 256>>>(x, Wq, Wk, Wv, cosb, sinb, nullptr);

    // 2. causal flash attention (bf16x3 MMA, cp.async pipeline)
    attn_kernel<<<dim3(16, 32), 256, 73728>>>();

    // 3. output projection
    gemm_bf16x3<1><<<dim3(8, 32), 256>>>(gy_dev, Wo, nullptr, nullptr, nullptr, nullptr, out);
}